// round 1
// baseline (speedup 1.0000x reference)
#include <cuda_runtime.h>
#include <cuda_bf16.h>

#define HID 90
#define HP 96          // padded hidden
#define NNODES 1024
#define BATCH 1024
#define TPB 256
#define ROWS 128       // samples per block
#define H1STRIDE 100   // padded row stride for h1 tile (bank-stagger)

// Per-node layer-1 bias (b1 + control-electrode contribution): 1024 x 96 floats.
__device__ float c1g[NNODES * HP];

__device__ __forceinline__ unsigned long long pack2(float x, float y) {
    unsigned long long r;
    asm("mov.b64 %0, {%1, %2};" : "=l"(r) : "f"(x), "f"(y));
    return r;
}
__device__ __forceinline__ void unpack2(unsigned long long v, float& x, float& y) {
    asm("mov.b64 {%0, %1}, %2;" : "=f"(x), "=f"(y) : "l"(v));
}
// Packed dual-fp32 FMA (sm_103a FFMA2) — 2x fp32 FMA throughput vs FFMA.
__device__ __forceinline__ void ffma2(unsigned long long& c, unsigned long long a,
                                      unsigned long long b) {
    asm("fma.rn.f32x2 %0, %1, %2, %0;" : "+l"(c) : "l"(a), "l"(b));
}

__device__ __forceinline__ float elu(float v) {
    return v > 0.f ? v : (__expf(v) - 1.f);
}

__global__ void precompute_c1_kernel(const float* __restrict__ controls,
                                     const float* __restrict__ W1,
                                     const float* __restrict__ b1,
                                     const int* __restrict__ control_list) {
    int n = blockIdx.x;       // 1024 blocks
    int j = threadIdx.x;      // 96 threads
    float v = 0.f;
    if (j < HID) {
        v = b1[j];
#pragma unroll
        for (int kk = 0; kk < 3; kk++) {
            int e = control_list[n * 3 + kk];
            v = fmaf(controls[n * 3 + kk], W1[e * HID + j], v);
        }
    }
    c1g[n * HP + j] = v;
}

struct SmemMain {
    float W2s[HP * HP];        // [k][j], zero-padded: 36864 B
    float h1s[ROWS * H1STRIDE];// 51200 B
    float W1s[7 * HP];         // zero-padded cols
    float pat[ROWS * 4];
    int   il[ROWS * 4];
    float W3s[HP];             // zero-padded
    float b2s[HP];             // zero-padded
};

__global__ void __launch_bounds__(TPB, 2)
lrf_main_kernel(const float* __restrict__ x,
                const float* __restrict__ W1,
                const float* __restrict__ W2,
                const float* __restrict__ b2,
                const float* __restrict__ W3,
                const float* __restrict__ b3,
                const int* __restrict__ inputs_list,
                float* __restrict__ out) {
    extern __shared__ char smem_raw[];
    SmemMain& s = *reinterpret_cast<SmemMain*>(smem_raw);
    const int tid = threadIdx.x;
    const int b  = blockIdx.x >> 3;            // batch image
    const int n0 = (blockIdx.x & 7) * ROWS;    // node tile base

    // ---- stage weights & per-block inputs ----
    for (int idx = tid; idx < HP * HP; idx += TPB) {
        int k = idx / HP, j = idx - k * HP;
        s.W2s[idx] = (k < HID && j < HID) ? W2[k * HID + j] : 0.f;
    }
    for (int idx = tid; idx < 7 * HP; idx += TPB) {
        int e = idx / HP, j = idx - e * HP;
        s.W1s[idx] = (j < HID) ? W1[e * HID + j] : 0.f;
    }
    if (tid < HP) {
        s.W3s[tid] = (tid < HID) ? W3[tid] : 0.f;
        s.b2s[tid] = (tid < HID) ? b2[tid] : 0.f;
    }
    if (tid < ROWS) {
        int n = n0 + tid;
        int pw = n & 31, ph = n >> 5;
        // x[b, 2*ph + kh, 2*pw + kw]; patch channel order kh*2+kw
        const float* xb = x + (size_t)b * 4096 + ph * 128 + pw * 2;
        float2 r0 = *reinterpret_cast<const float2*>(xb);
        float2 r1 = *reinterpret_cast<const float2*>(xb + 64);
        s.pat[tid * 4 + 0] = r0.x; s.pat[tid * 4 + 1] = r0.y;
        s.pat[tid * 4 + 2] = r1.x; s.pat[tid * 4 + 3] = r1.y;
        *reinterpret_cast<int4*>(&s.il[tid * 4]) =
            *reinterpret_cast<const int4*>(inputs_list + n * 4);
    }
    __syncthreads();

    // ---- phase 1: h1 = elu(c1[n] + sum_i patch_i * W1[row_i]) ----
    // Padded cols (j>=90) come out exactly 0 (c1g pad=0, W1s pad=0, elu(0)=0).
#pragma unroll 4
    for (int e = 0; e < (ROWS * HP) / TPB; e++) {
        int idx = e * TPB + tid;
        int r = idx / HP, j = idx - r * HP;
        int4 ii = *reinterpret_cast<int4*>(&s.il[r * 4]);
        float p0 = s.pat[r * 4 + 0], p1 = s.pat[r * 4 + 1];
        float p2 = s.pat[r * 4 + 2], p3 = s.pat[r * 4 + 3];
        float v = c1g[(n0 + r) * HP + j];
        v = fmaf(p0, s.W1s[ii.x * HP + j], v);
        v = fmaf(p1, s.W1s[ii.y * HP + j], v);
        v = fmaf(p2, s.W1s[ii.z * HP + j], v);
        v = fmaf(p3, s.W1s[ii.w * HP + j], v);
        s.h1s[r * H1STRIDE + j] = elu(v);
    }
    __syncthreads();

    // ---- phase 2: h2 = h1 @ W2 + b2, 4 rows x 12 cols per thread, f32x2 ----
    const int cg = tid & 7, rg = tid >> 3;
    const int r0 = rg * 4, c0 = cg * 12;
    unsigned long long acc[4][6];
#pragma unroll
    for (int i = 0; i < 4; i++)
#pragma unroll
        for (int m = 0; m < 6; m++)
            acc[i][m] = pack2(s.b2s[c0 + 2 * m], s.b2s[c0 + 2 * m + 1]);

#pragma unroll 2
    for (int kb = 0; kb < HP / 4; kb++) {
        float4 a[4];
#pragma unroll
        for (int i = 0; i < 4; i++)
            a[i] = *reinterpret_cast<float4*>(&s.h1s[(r0 + i) * H1STRIDE + kb * 4]);
#pragma unroll
        for (int dk = 0; dk < 4; dk++) {
            const float* wrow = &s.W2s[(kb * 4 + dk) * HP + c0];
            float4 w0 = *reinterpret_cast<const float4*>(wrow);
            float4 w1 = *reinterpret_cast<const float4*>(wrow + 4);
            float4 w2 = *reinterpret_cast<const float4*>(wrow + 8);
            unsigned long long bp[6] = {
                pack2(w0.x, w0.y), pack2(w0.z, w0.w),
                pack2(w1.x, w1.y), pack2(w1.z, w1.w),
                pack2(w2.x, w2.y), pack2(w2.z, w2.w)};
#pragma unroll
            for (int i = 0; i < 4; i++) {
                float av = (dk == 0) ? a[i].x : (dk == 1) ? a[i].y
                         : (dk == 2) ? a[i].z : a[i].w;
                unsigned long long ap = pack2(av, av);
#pragma unroll
                for (int m = 0; m < 6; m++) ffma2(acc[i][m], ap, bp[m]);
            }
        }
    }

    // ---- phase 3: out = elu(h2) @ W3 + b3, butterfly over the 8 cg lanes ----
    const float b3v = b3[0];
#pragma unroll
    for (int i = 0; i < 4; i++) {
        float part = 0.f;
#pragma unroll
        for (int m = 0; m < 6; m++) {
            float h0, h1v;
            unpack2(acc[i][m], h0, h1v);
            part = fmaf(elu(h0),  s.W3s[c0 + 2 * m],     part);
            part = fmaf(elu(h1v), s.W3s[c0 + 2 * m + 1], part);
        }
#pragma unroll
        for (int off = 1; off < 8; off <<= 1)
            part += __shfl_xor_sync(0xffffffffu, part, off);
        if (cg == 0)
            out[(size_t)b * NNODES + n0 + r0 + i] = part + b3v;
    }
}

extern "C" void kernel_launch(void* const* d_in, const int* in_sizes, int n_in,
                              void* d_out, int out_size) {
    const float* x            = (const float*)d_in[0];
    const float* controls     = (const float*)d_in[1];
    const float* W1           = (const float*)d_in[2];
    const float* b1           = (const float*)d_in[3];
    const float* W2           = (const float*)d_in[4];
    const float* b2           = (const float*)d_in[5];
    const float* W3           = (const float*)d_in[6];
    const float* b3           = (const float*)d_in[7];
    const int*   inputs_list  = (const int*)d_in[8];
    const int*   control_list = (const int*)d_in[9];
    float* out = (float*)d_out;

    cudaFuncSetAttribute(lrf_main_kernel,
                         cudaFuncAttributeMaxDynamicSharedMemorySize,
                         (int)sizeof(SmemMain));

    precompute_c1_kernel<<<NNODES, HP>>>(controls, W1, b1, control_list);
    lrf_main_kernel<<<BATCH * (NNODES / ROWS), TPB, sizeof(SmemMain)>>>(
        x, W1, W2, b2, W3, b3, inputs_list, out);
}

// round 3
// speedup vs baseline: 1.8283x; 1.8283x over previous
#include <cuda_runtime.h>
#include <cuda_bf16.h>
#include <cstdint>

#define HID 90
#define HP 96
#define NNODES 1024
#define BATCH 1024
#define TPB 256
#define ROWS 128
#define RSTRIDE 208          // bytes per smem matrix row (104 bf16) — conflict-free ldmatrix

// ---------------- device globals (no allocation allowed) ----------------
__device__ float c1g[NNODES * HP];                       // per-node layer-1 bias
__device__ __align__(16) unsigned char Bimg[39936];      // W2^T bf16 hi (19968) + lo

// ---------------- smem layout ----------------
#define SM_A_HI 0
#define SM_A_LO 26624
#define SM_B_HI 53248
#define SM_B_LO 73216
#define SM_W1   93184
#define SM_BW   95872
#define SM_PAT  96640
#define SM_IL   98688
#define SM_TOTAL 100736

__device__ __forceinline__ uint32_t smem_u32(const void* p) {
    uint32_t a;
    asm("{ .reg .u64 t; cvta.to.shared.u64 t, %1; cvt.u32.u64 %0, t; }"
        : "=r"(a) : "l"(p));
    return a;
}
__device__ __forceinline__ void ldsm_x4(uint32_t& r0, uint32_t& r1,
                                        uint32_t& r2, uint32_t& r3, uint32_t a) {
    asm volatile("ldmatrix.sync.aligned.m8n8.x4.shared.b16 {%0,%1,%2,%3}, [%4];"
                 : "=r"(r0), "=r"(r1), "=r"(r2), "=r"(r3) : "r"(a));
}
__device__ __forceinline__ void mma16816(float* c, uint32_t a0, uint32_t a1,
                                         uint32_t a2, uint32_t a3,
                                         uint32_t b0, uint32_t b1) {
    asm volatile(
        "mma.sync.aligned.m16n8k16.row.col.f32.bf16.bf16.f32 "
        "{%0,%1,%2,%3}, {%4,%5,%6,%7}, {%8,%9}, {%0,%1,%2,%3};"
        : "+f"(c[0]), "+f"(c[1]), "+f"(c[2]), "+f"(c[3])
        : "r"(a0), "r"(a1), "r"(a2), "r"(a3), "r"(b0), "r"(b1));
}
__device__ __forceinline__ float elu(float v) {
    return v > 0.f ? v : (__expf(v) - 1.f);
}

// ---------------- prep kernels ----------------
__global__ void precompute_c1_kernel(const float* __restrict__ controls,
                                     const float* __restrict__ W1,
                                     const float* __restrict__ b1,
                                     const int* __restrict__ control_list) {
    int n = blockIdx.x;
    int j = threadIdx.x;  // 96
    float v = 0.f;
    if (j < HID) {
        v = b1[j];
#pragma unroll
        for (int kk = 0; kk < 3; kk++) {
            int e = control_list[n * 3 + kk];
            v = fmaf(controls[n * 3 + kk], W1[e * HID + j], v);
        }
    }
    c1g[n * HP + j] = v;
}

// Bimg[n][k] = bf16 split of W2[k][n]; row-major n (96 rows), stride 208 B.
__global__ void prep_b_kernel(const float* __restrict__ W2) {
    int idx = blockIdx.x * 256 + threadIdx.x;
    if (idx >= HP * HP) return;
    int n = idx / HP, k = idx - n * HP;
    float v = (n < HID && k < HID) ? W2[k * HID + n] : 0.f;
    __nv_bfloat16 h = __float2bfloat16(v);
    __nv_bfloat16 l = __float2bfloat16(v - __bfloat162float(h));
    uint32_t off = (uint32_t)n * RSTRIDE + (uint32_t)k * 2;
    *(__nv_bfloat16*)(Bimg + off) = h;
    *(__nv_bfloat16*)(Bimg + 19968 + off) = l;
}

// ---------------- main kernel ----------------
__global__ void __launch_bounds__(TPB, 2)
lrf_main_kernel(const float* __restrict__ x,
                const float* __restrict__ W1,
                const float* __restrict__ b2,
                const float* __restrict__ W3,
                const float* __restrict__ b3,
                const int* __restrict__ inputs_list,
                float* __restrict__ out) {
    extern __shared__ char sm[];
    const uint32_t smb = smem_u32(sm);
    const int tid = threadIdx.x;
    const int wid = tid >> 5, lid = tid & 31;
    const int b  = blockIdx.x >> 3;
    const int n0 = (blockIdx.x & 7) * ROWS;

    // ---- stage B (hi+lo, 39936 B contiguous) ----
    {
        const uint4* src = (const uint4*)Bimg;
        uint4* dst = (uint4*)(sm + SM_B_HI);
        for (int i = tid; i < 39936 / 16; i += TPB) dst[i] = src[i];
    }
    // ---- stage W1 (zero-pad cols), fused [b2,W3] table ----
    for (int idx = tid; idx < 7 * HP; idx += TPB) {
        int e = idx / HP, j = idx - e * HP;
        ((float*)(sm + SM_W1))[idx] = (j < HID) ? W1[e * HID + j] : 0.f;
    }
    if (tid < HP) {
        float bb = (tid < HID) ? b2[tid] : 0.f;
        float ww = (tid < HID) ? W3[tid] : 0.f;
        ((float*)(sm + SM_BW))[tid * 2]     = bb;
        ((float*)(sm + SM_BW))[tid * 2 + 1] = ww;
    }
    // ---- stage patches + electrode indices ----
    if (tid < ROWS) {
        int n = n0 + tid;
        int pw = n & 31, ph = n >> 5;
        const float* xb = x + (size_t)b * 4096 + ph * 128 + pw * 2;
        float2 r0 = *reinterpret_cast<const float2*>(xb);
        float2 r1 = *reinterpret_cast<const float2*>(xb + 64);
        *reinterpret_cast<float4*>(sm + SM_PAT + tid * 16) =
            make_float4(r0.x, r0.y, r1.x, r1.y);
        *reinterpret_cast<int4*>(sm + SM_IL + tid * 16) =
            *reinterpret_cast<const int4*>(inputs_list + n * 4);
    }
    __syncthreads();

    // ---- phase 1: h1 = elu(c1 + patch·W1rows), bf16 hi/lo into A tiles ----
#pragma unroll
    for (int it = 0; it < 6; it++) {
        int item = it * TPB + tid;          // 128 rows x 12 col-groups
        int r = item / 12, jg = item - r * 12;
        int j0 = jg * 8;
        float4 pv = *reinterpret_cast<float4*>(sm + SM_PAT + r * 16);
        int4 ii = *reinterpret_cast<int4*>(sm + SM_IL + r * 16);
        const float* W1s = (const float*)(sm + SM_W1);
        const float* c1p = c1g + (n0 + r) * HP + j0;
        float4 v0 = *reinterpret_cast<const float4*>(c1p);
        float4 v1 = *reinterpret_cast<const float4*>(c1p + 4);
        float v[8] = {v0.x, v0.y, v0.z, v0.w, v1.x, v1.y, v1.z, v1.w};
#pragma unroll
        for (int q = 0; q < 8; q++) {
            v[q] = fmaf(pv.x, W1s[ii.x * HP + j0 + q], v[q]);
            v[q] = fmaf(pv.y, W1s[ii.y * HP + j0 + q], v[q]);
            v[q] = fmaf(pv.z, W1s[ii.z * HP + j0 + q], v[q]);
            v[q] = fmaf(pv.w, W1s[ii.w * HP + j0 + q], v[q]);
        }
        uint32_t hi[4], lo[4];
#pragma unroll
        for (int q = 0; q < 4; q++) {
            float a = elu(v[2 * q]), c = elu(v[2 * q + 1]);
            __nv_bfloat16 ha = __float2bfloat16(a), hc = __float2bfloat16(c);
            __nv_bfloat16 la = __float2bfloat16(a - __bfloat162float(ha));
            __nv_bfloat16 lc = __float2bfloat16(c - __bfloat162float(hc));
            hi[q] = (uint32_t)__bfloat16_as_ushort(ha)
                  | ((uint32_t)__bfloat16_as_ushort(hc) << 16);
            lo[q] = (uint32_t)__bfloat16_as_ushort(la)
                  | ((uint32_t)__bfloat16_as_ushort(lc) << 16);
        }
        uint32_t off = (uint32_t)r * RSTRIDE + (uint32_t)j0 * 2;
        *reinterpret_cast<uint4*>(sm + SM_A_HI + off) = make_uint4(hi[0], hi[1], hi[2], hi[3]);
        *reinterpret_cast<uint4*>(sm + SM_A_LO + off) = make_uint4(lo[0], lo[1], lo[2], lo[3]);
    }
    __syncthreads();

    // ---- phase 2: C = A·B via mma.sync m16n8k16, 3-pass bf16 split ----
    float acc[12][4];
#pragma unroll
    for (int nt = 0; nt < 12; nt++)
#pragma unroll
        for (int q = 0; q < 4; q++) acc[nt][q] = 0.f;

    // per-lane ldmatrix row offsets
    const uint32_t aRow = (uint32_t)(wid * 16 + (lid & 7) + ((lid >> 3) & 1) * 8) * RSTRIDE
                        + (uint32_t)(lid >> 4) * 16;
    const uint32_t bRowBase = (uint32_t)((lid & 7) + (lid >> 4) * 8) * RSTRIDE
                            + (uint32_t)((lid >> 3) & 1) * 16;

    const uint32_t aBase[3] = {smb + SM_A_HI, smb + SM_A_LO, smb + SM_A_HI};
    const uint32_t bBase[3] = {smb + SM_B_HI, smb + SM_B_HI, smb + SM_B_LO};

#pragma unroll
    for (int p = 0; p < 3; p++) {
        uint32_t aB = aBase[p] + aRow, bB = bBase[p] + bRowBase;
#pragma unroll
        for (int kk = 0; kk < 6; kk++) {
            uint32_t a0, a1, a2, a3;
            ldsm_x4(a0, a1, a2, a3, aB + kk * 32);
#pragma unroll
            for (int nt2 = 0; nt2 < 6; nt2++) {
                uint32_t b0, b1, b2r, b3r;
                ldsm_x4(b0, b1, b2r, b3r, bB + (uint32_t)nt2 * 16 * RSTRIDE + kk * 32);
                mma16816(acc[2 * nt2],     a0, a1, a2, a3, b0,  b1);
                mma16816(acc[2 * nt2 + 1], a0, a1, a2, a3, b2r, b3r);
            }
        }
    }

    // ---- phase 3: out = elu(C + b2) · W3 + b3, shfl-reduce over col lanes ----
    const float b3v = b3[0];
    float part0 = 0.f, part1 = 0.f;
    const char* bwp = sm + SM_BW + (size_t)(lid & 3) * 16;
#pragma unroll
    for (int nt = 0; nt < 12; nt++) {
        float4 bw = *reinterpret_cast<const float4*>(bwp + nt * 64);
        part0 = fmaf(elu(acc[nt][0] + bw.x), bw.y, part0);
        part0 = fmaf(elu(acc[nt][1] + bw.z), bw.w, part0);
        part1 = fmaf(elu(acc[nt][2] + bw.x), bw.y, part1);
        part1 = fmaf(elu(acc[nt][3] + bw.z), bw.w, part1);
    }
#pragma unroll
    for (int off = 1; off < 4; off <<= 1) {
        part0 += __shfl_xor_sync(0xffffffffu, part0, off);
        part1 += __shfl_xor_sync(0xffffffffu, part1, off);
    }
    if ((lid & 3) == 0) {
        int g = n0 + wid * 16 + (lid >> 2);
        out[(size_t)b * NNODES + g]     = part0 + b3v;
        out[(size_t)b * NNODES + g + 8] = part1 + b3v;
    }
}

extern "C" void kernel_launch(void* const* d_in, const int* in_sizes, int n_in,
                              void* d_out, int out_size) {
    const float* x            = (const float*)d_in[0];
    const float* controls     = (const float*)d_in[1];
    const float* W1           = (const float*)d_in[2];
    const float* b1           = (const float*)d_in[3];
    const float* W2           = (const float*)d_in[4];
    const float* b2           = (const float*)d_in[5];
    const float* W3           = (const float*)d_in[6];
    const float* b3           = (const float*)d_in[7];
    const int*   inputs_list  = (const int*)d_in[8];
    const int*   control_list = (const int*)d_in[9];
    float* out = (float*)d_out;

    cudaFuncSetAttribute(lrf_main_kernel,
                         cudaFuncAttributeMaxDynamicSharedMemorySize, SM_TOTAL);

    precompute_c1_kernel<<<NNODES, HP>>>(controls, W1, b1, control_list);
    prep_b_kernel<<<(HP * HP + 255) / 256, 256>>>(W2);
    lrf_main_kernel<<<BATCH * (NNODES / ROWS), TPB, SM_TOTAL>>>(
        x, W1, b2, W3, b3, inputs_list, out);
}